// round 1
// baseline (speedup 1.0000x reference)
#include <cuda_runtime.h>
#include <math.h>

#define NQ   1024
#define CDIM 256
#define NCAM 6
#define NLVL 4
#define EPSF 1e-5f

// Scratch (static device globals — no allocation allowed)
__device__ float g_qe[NQ * CDIM];
__device__ float g_attw[NQ * NCAM * NLVL];
__device__ float g_mid[NQ * CDIM];

// ---------------------------------------------------------------------------
// Kernel 1: qe = (query+query_pos) @ W_qe + b_qe ; attw = sigmoid(qe@W_attn+b)
// One block per query, 256 threads.
// ---------------------------------------------------------------------------
__global__ void k_qe(const float* __restrict__ query,
                     const float* __restrict__ query_pos,
                     const float* __restrict__ W_qe,
                     const float* __restrict__ b_qe,
                     const float* __restrict__ W_attn,
                     const float* __restrict__ b_attn) {
    int q = blockIdx.x, t = threadIdx.x;
    __shared__ float sx[64];
    __shared__ float sqe[CDIM];
    if (t < 64) sx[t] = query[q * 64 + t] + query_pos[q * 64 + t];
    __syncthreads();
    float acc = __ldg(&b_qe[t]);
#pragma unroll 8
    for (int k = 0; k < 64; k++) acc += sx[k] * __ldg(&W_qe[k * CDIM + t]);
    sqe[t] = acc;
    g_qe[q * CDIM + t] = acc;
    __syncthreads();
    if (t < 24) {
        float a = __ldg(&b_attn[t]);
#pragma unroll 8
        for (int k = 0; k < CDIM; k++) a += sqe[k] * __ldg(&W_attn[k * 24 + t]);
        g_attw[q * 24 + t] = 1.0f / (1.0f + expf(-a));
    }
}

// ---------------------------------------------------------------------------
// Kernel 2: project reference points to each camera, bilinear-gather all
// levels, weight by sigmoid(attw)*mask*tapweight, sum -> g_mid[q][c].
// One block per query, 256 threads (one per channel).
// ---------------------------------------------------------------------------
__global__ void k_gather(const float* __restrict__ refp,
                         const float* __restrict__ l2i,
                         const float* __restrict__ f0,
                         const float* __restrict__ f1,
                         const float* __restrict__ f2,
                         const float* __restrict__ f3) {
    int q = blockIdx.x, t = threadIdx.x;
    __shared__ float s_gx[NCAM], s_gy[NCAM];
    __shared__ int   s_m[NCAM];
    __shared__ int   s_o00[24], s_o01[24], s_o10[24], s_o11[24];
    __shared__ float s_w00[24], s_w01[24], s_w10[24], s_w11[24];

    if (t < NCAM) {
        float rx = __ldg(&refp[q * 3 + 0]);
        float ry = __ldg(&refp[q * 3 + 1]);
        float rz = __ldg(&refp[q * 3 + 2]);
        const float* M = l2i + t * 16;
        float px = __ldg(&M[0]) * rx + __ldg(&M[1]) * ry + __ldg(&M[2]) * rz + __ldg(&M[3]);
        float py = __ldg(&M[4]) * rx + __ldg(&M[5]) * ry + __ldg(&M[6]) * rz + __ldg(&M[7]);
        float pz = __ldg(&M[8]) * rx + __ldg(&M[9]) * ry + __ldg(&M[10]) * rz + __ldg(&M[11]);
        int front = pz > EPSF;
        float zc = fmaxf(pz, EPSF);
        float gx = (px / zc / 1600.0f - 0.5f) * 2.0f;
        float gy = (py / zc / 928.0f - 0.5f) * 2.0f;
        int inb = (gx > -1.0f) && (gx < 1.0f) && (gy > -1.0f) && (gy < 1.0f);
        s_gx[t] = gx;
        s_gy[t] = gy;
        s_m[t] = front && inb;
    }
    __syncthreads();
    if (t < 24) {
        const int Hs[4] = {116, 58, 29, 15};
        const int Ws[4] = {200, 100, 50, 25};
        int n = t >> 2, l = t & 3;
        int H = Hs[l], W = Ws[l];
        float wnl = g_attw[q * 24 + t] * (s_m[n] ? 1.0f : 0.0f);
        float x = ((s_gx[n] + 1.0f) * (float)W - 1.0f) * 0.5f;
        float y = ((s_gy[n] + 1.0f) * (float)H - 1.0f) * 0.5f;
        float xf = floorf(x), yf = floorf(y);
        int ix0 = (int)xf, iy0 = (int)yf;
        float fx = x - xf, fy = y - yf;
        int ix1 = ix0 + 1, iy1 = iy0 + 1;
        float vx0 = (ix0 >= 0 && ix0 < W) ? 1.0f : 0.0f;
        float vx1 = (ix1 >= 0 && ix1 < W) ? 1.0f : 0.0f;
        float vy0 = (iy0 >= 0 && iy0 < H) ? 1.0f : 0.0f;
        float vy1 = (iy1 >= 0 && iy1 < H) ? 1.0f : 0.0f;
        int cx0 = min(max(ix0, 0), W - 1), cx1 = min(max(ix1, 0), W - 1);
        int cy0 = min(max(iy0, 0), H - 1), cy1 = min(max(iy1, 0), H - 1);
        s_o00[t] = cy0 * W + cx0; s_o01[t] = cy0 * W + cx1;
        s_o10[t] = cy1 * W + cx0; s_o11[t] = cy1 * W + cx1;
        s_w00[t] = wnl * (1.0f - fy) * (1.0f - fx) * vy0 * vx0;
        s_w01[t] = wnl * (1.0f - fy) * fx * vy0 * vx1;
        s_w10[t] = wnl * fy * (1.0f - fx) * vy1 * vx0;
        s_w11[t] = wnl * fy * fx * vy1 * vx1;
    }
    __syncthreads();

    const float* fp[NLVL] = {f0, f1, f2, f3};
    const int HWs[NLVL] = {23200, 5800, 1450, 375};
    float acc = 0.0f;
#pragma unroll
    for (int n = 0; n < NCAM; n++) {
        if (!s_m[n]) continue;
#pragma unroll
        for (int l = 0; l < NLVL; l++) {
            int idx = n * 4 + l;
            const float* base = fp[l] + (size_t)(n * CDIM + t) * HWs[l];
            acc += s_w00[idx] * __ldg(base + s_o00[idx])
                 + s_w01[idx] * __ldg(base + s_o01[idx])
                 + s_w10[idx] * __ldg(base + s_o10[idx])
                 + s_w11[idx] * __ldg(base + s_o11[idx]);
        }
    }
    g_mid[q * CDIM + t] = acc;
}

// ---------------------------------------------------------------------------
// block-wide sum over 256 threads
// ---------------------------------------------------------------------------
__device__ __forceinline__ float block_sum(float v, float* sr, int t) {
    sr[t] = v;
    __syncthreads();
#pragma unroll
    for (int s = 128; s > 0; s >>= 1) {
        if (t < s) sr[t] += sr[t + s];
        __syncthreads();
    }
    float r = sr[0];
    __syncthreads();
    return r;
}

// ---------------------------------------------------------------------------
// Kernel 3: pos-MLP (2x LN+relu) + out@W_out + residuals + @W_fin + final LN
// One block per query, 256 threads.
// ---------------------------------------------------------------------------
__global__ void k_tail(const float* __restrict__ refp,
                       const float* __restrict__ pe_w1, const float* __restrict__ pe_b1,
                       const float* __restrict__ pe_g1, const float* __restrict__ pe_be1,
                       const float* __restrict__ pe_w2, const float* __restrict__ pe_b2,
                       const float* __restrict__ pe_g2, const float* __restrict__ pe_be2,
                       const float* __restrict__ W_out, const float* __restrict__ b_out,
                       const float* __restrict__ W_fin, const float* __restrict__ b_fin,
                       const float* __restrict__ g_norm, const float* __restrict__ b_norm,
                       float* __restrict__ outp) {
    int q = blockIdx.x, t = threadIdx.x;
    __shared__ float sa[CDIM];
    __shared__ float sr[CDIM];
    __shared__ float sy[64];

    // ---- pos layer 1: ref @ pe_w1 + b, LN, relu ----
    float rx = __ldg(&refp[q * 3 + 0]);
    float ry = __ldg(&refp[q * 3 + 1]);
    float rz = __ldg(&refp[q * 3 + 2]);
    float p1 = __ldg(&pe_b1[t]) + rx * __ldg(&pe_w1[t])
             + ry * __ldg(&pe_w1[256 + t]) + rz * __ldg(&pe_w1[512 + t]);
    float m = block_sum(p1, sr, t) * (1.0f / 256.0f);
    float d = p1 - m;
    float var = block_sum(d * d, sr, t) * (1.0f / 256.0f);
    float a = d * rsqrtf(var + EPSF) * __ldg(&pe_g1[t]) + __ldg(&pe_be1[t]);
    a = fmaxf(a, 0.0f);
    sa[t] = a;
    __syncthreads();

    // ---- pos layer 2: @ pe_w2, LN, relu ----
    float p2 = __ldg(&pe_b2[t]);
#pragma unroll 8
    for (int k = 0; k < CDIM; k++) p2 += sa[k] * __ldg(&pe_w2[k * CDIM + t]);
    m = block_sum(p2, sr, t) * (1.0f / 256.0f);
    d = p2 - m;
    var = block_sum(d * d, sr, t) * (1.0f / 256.0f);
    float pos = fmaxf(d * rsqrtf(var + EPSF) * __ldg(&pe_g2[t]) + __ldg(&pe_be2[t]), 0.0f);
    __syncthreads();

    // ---- out2 = mid @ W_out + b_out ----
    sa[t] = g_mid[q * CDIM + t];
    __syncthreads();
    float o2 = __ldg(&b_out[t]);
#pragma unroll 8
    for (int k = 0; k < CDIM; k++) o2 += sa[k] * __ldg(&W_out[k * CDIM + t]);

    float sum = o2 + g_qe[q * CDIM + t] + pos;
    __syncthreads();
    sa[t] = sum;
    __syncthreads();

    // ---- y = sum @ W_fin + b_fin  (64 outputs) ----
    if (t < 64) {
        float y = __ldg(&b_fin[t]);
#pragma unroll 8
        for (int k = 0; k < CDIM; k++) y += sa[k] * __ldg(&W_fin[k * 64 + t]);
        sy[t] = y;
    }
    __syncthreads();

    // ---- final LN over 64 ----
    if (t < 64) {
        float mm = 0.0f;
#pragma unroll
        for (int k = 0; k < 64; k++) mm += sy[k];
        mm *= (1.0f / 64.0f);
        float vv = 0.0f;
#pragma unroll
        for (int k = 0; k < 64; k++) {
            float dd = sy[k] - mm;
            vv += dd * dd;
        }
        vv *= (1.0f / 64.0f);
        outp[q * 64 + t] = (sy[t] - mm) * rsqrtf(vv + EPSF) * __ldg(&g_norm[t]) + __ldg(&b_norm[t]);
    }
}

// ---------------------------------------------------------------------------
extern "C" void kernel_launch(void* const* d_in, const int* in_sizes, int n_in,
                              void* d_out, int out_size) {
    const float* query   = (const float*)d_in[0];
    const float* qpos    = (const float*)d_in[1];
    const float* refp    = (const float*)d_in[2];
    const float* l2i     = (const float*)d_in[3];
    const float* f0      = (const float*)d_in[4];
    const float* f1      = (const float*)d_in[5];
    const float* f2      = (const float*)d_in[6];
    const float* f3      = (const float*)d_in[7];
    const float* W_qe    = (const float*)d_in[8];
    const float* b_qe    = (const float*)d_in[9];
    const float* W_attn  = (const float*)d_in[10];
    const float* b_attn  = (const float*)d_in[11];
    const float* W_out   = (const float*)d_in[12];
    const float* b_out   = (const float*)d_in[13];
    const float* pe_w1   = (const float*)d_in[14];
    const float* pe_b1   = (const float*)d_in[15];
    const float* pe_g1   = (const float*)d_in[16];
    const float* pe_be1  = (const float*)d_in[17];
    const float* pe_w2   = (const float*)d_in[18];
    const float* pe_b2   = (const float*)d_in[19];
    const float* pe_g2   = (const float*)d_in[20];
    const float* pe_be2  = (const float*)d_in[21];
    const float* W_fin   = (const float*)d_in[22];
    const float* b_fin   = (const float*)d_in[23];
    const float* g_norm  = (const float*)d_in[24];
    const float* b_norm  = (const float*)d_in[25];
    float* outp = (float*)d_out;

    k_qe<<<NQ, 256>>>(query, qpos, W_qe, b_qe, W_attn, b_attn);
    k_gather<<<NQ, 256>>>(refp, l2i, f0, f1, f2, f3);
    k_tail<<<NQ, 256>>>(refp, pe_w1, pe_b1, pe_g1, pe_be1,
                        pe_w2, pe_b2, pe_g2, pe_be2,
                        W_out, b_out, W_fin, b_fin, g_norm, b_norm, outp);
}

// round 3
// speedup vs baseline: 1.5598x; 1.5598x over previous
#include <cuda_runtime.h>
#include <math.h>

#define NQ   1024
#define CDIM 256
#define NCAM 6
#define NLVL 4
#define EPSF 1e-5f
#define QB   4

// Scratch (static device globals — no allocation allowed)
__device__ float g_qe[NQ * CDIM];
__device__ float g_attw[NQ * NCAM * NLVL];
__device__ float g_mid[NQ * CDIM];

// ---------------------------------------------------------------------------
// Kernel 1: qe = (query+query_pos) @ W_qe + b_qe ; attw = sigmoid(qe@W_attn+b)
// QB=4 queries per block, 256 threads. attw via warp-parallel reduction.
// ---------------------------------------------------------------------------
__global__ void __launch_bounds__(256) k_qe(
        const float* __restrict__ query,
        const float* __restrict__ query_pos,
        const float* __restrict__ W_qe,
        const float* __restrict__ b_qe,
        const float* __restrict__ W_attn,
        const float* __restrict__ b_attn) {
    int q0 = blockIdx.x * QB, t = threadIdx.x;
    __shared__ float sx[QB * 64];
    __shared__ float sqe[QB * CDIM];
    __shared__ float sW[24 * 257];          // W_attn transposed [o][k], padded

    if (t < QB * 64) {
        int r = t >> 6, k = t & 63;
        sx[t] = query[(q0 + r) * 64 + k] + query_pos[(q0 + r) * 64 + k];
    }
    // coalesced load of W_attn (k-major in gmem) -> sW[o][k]
#pragma unroll
    for (int i = 0; i < 24; i++) {
        int idx = t + i * 256;              // idx < 6144
        int k = idx / 24, o = idx % 24;
        sW[o * 257 + k] = __ldg(&W_attn[idx]);
    }
    __syncthreads();

    float bb = __ldg(&b_qe[t]);
    float a0 = bb, a1 = bb, a2 = bb, a3 = bb;
#pragma unroll 8
    for (int k = 0; k < 64; k++) {
        float w = __ldg(&W_qe[k * CDIM + t]);
        a0 += sx[k] * w;
        a1 += sx[64 + k] * w;
        a2 += sx[128 + k] * w;
        a3 += sx[192 + k] * w;
    }
    sqe[t] = a0;           g_qe[(q0 + 0) * CDIM + t] = a0;
    sqe[256 + t] = a1;     g_qe[(q0 + 1) * CDIM + t] = a1;
    sqe[512 + t] = a2;     g_qe[(q0 + 2) * CDIM + t] = a2;
    sqe[768 + t] = a3;     g_qe[(q0 + 3) * CDIM + t] = a3;
    __syncthreads();

    // 96 tasks (24 outputs x 4 queries), 12 per warp
    int wid = t >> 5, lane = t & 31;
#pragma unroll
    for (int m = wid * 12; m < wid * 12 + 12; m++) {
        int o = m >> 2, r = m & 3;
        float s = 0.0f;
#pragma unroll
        for (int i = 0; i < 8; i++) {
            int k = lane + i * 32;
            s += sqe[r * 256 + k] * sW[o * 257 + k];
        }
#pragma unroll
        for (int off = 16; off; off >>= 1) s += __shfl_down_sync(0xffffffffu, s, off);
        if (lane == 0) {
            s += __ldg(&b_attn[o]);
            g_attw[(q0 + r) * 24 + o] = 1.0f / (1.0f + __expf(-s));
        }
    }
}

// ---------------------------------------------------------------------------
// Kernel 2: project reference points, bilinear-gather all cams/levels,
// weighted sum -> g_mid[q][c]. One block per query, 256 threads.
// ---------------------------------------------------------------------------
__global__ void __launch_bounds__(256) k_gather(
        const float* __restrict__ refp,
        const float* __restrict__ l2i,
        const float* __restrict__ f0,
        const float* __restrict__ f1,
        const float* __restrict__ f2,
        const float* __restrict__ f3) {
    int q = blockIdx.x, t = threadIdx.x;
    __shared__ float s_gx[NCAM], s_gy[NCAM];
    __shared__ int   s_m[NCAM];
    __shared__ int   s_o00[24], s_o01[24], s_o10[24], s_o11[24];
    __shared__ float s_w00[24], s_w01[24], s_w10[24], s_w11[24];

    if (t < NCAM) {
        float rx = __ldg(&refp[q * 3 + 0]);
        float ry = __ldg(&refp[q * 3 + 1]);
        float rz = __ldg(&refp[q * 3 + 2]);
        const float* M = l2i + t * 16;
        float px = __ldg(&M[0]) * rx + __ldg(&M[1]) * ry + __ldg(&M[2]) * rz + __ldg(&M[3]);
        float py = __ldg(&M[4]) * rx + __ldg(&M[5]) * ry + __ldg(&M[6]) * rz + __ldg(&M[7]);
        float pz = __ldg(&M[8]) * rx + __ldg(&M[9]) * ry + __ldg(&M[10]) * rz + __ldg(&M[11]);
        int front = pz > EPSF;
        float zc = fmaxf(pz, EPSF);
        float gx = (px / zc / 1600.0f - 0.5f) * 2.0f;
        float gy = (py / zc / 928.0f - 0.5f) * 2.0f;
        int inb = (gx > -1.0f) && (gx < 1.0f) && (gy > -1.0f) && (gy < 1.0f);
        s_gx[t] = gx;
        s_gy[t] = gy;
        s_m[t] = front && inb;
    }
    __syncthreads();
    if (t < 24) {
        const int Hs[4] = {116, 58, 29, 15};
        const int Ws[4] = {200, 100, 50, 25};
        int n = t >> 2, l = t & 3;
        int H = Hs[l], W = Ws[l];
        float wnl = g_attw[q * 24 + t] * (s_m[n] ? 1.0f : 0.0f);
        float x = ((s_gx[n] + 1.0f) * (float)W - 1.0f) * 0.5f;
        float y = ((s_gy[n] + 1.0f) * (float)H - 1.0f) * 0.5f;
        float xf = floorf(x), yf = floorf(y);
        int ix0 = (int)xf, iy0 = (int)yf;
        float fx = x - xf, fy = y - yf;
        int ix1 = ix0 + 1, iy1 = iy0 + 1;
        float vx0 = (ix0 >= 0 && ix0 < W) ? 1.0f : 0.0f;
        float vx1 = (ix1 >= 0 && ix1 < W) ? 1.0f : 0.0f;
        float vy0 = (iy0 >= 0 && iy0 < H) ? 1.0f : 0.0f;
        float vy1 = (iy1 >= 0 && iy1 < H) ? 1.0f : 0.0f;
        int cx0 = min(max(ix0, 0), W - 1), cx1 = min(max(ix1, 0), W - 1);
        int cy0 = min(max(iy0, 0), H - 1), cy1 = min(max(iy1, 0), H - 1);
        s_o00[t] = cy0 * W + cx0; s_o01[t] = cy0 * W + cx1;
        s_o10[t] = cy1 * W + cx0; s_o11[t] = cy1 * W + cx1;
        s_w00[t] = wnl * (1.0f - fy) * (1.0f - fx) * vy0 * vx0;
        s_w01[t] = wnl * (1.0f - fy) * fx * vy0 * vx1;
        s_w10[t] = wnl * fy * (1.0f - fx) * vy1 * vx0;
        s_w11[t] = wnl * fy * fx * vy1 * vx1;
    }
    __syncthreads();

    const float* fp[NLVL] = {f0, f1, f2, f3};
    const int HWs[NLVL] = {23200, 5800, 1450, 375};
    float acc0 = 0.0f, acc1 = 0.0f;
#pragma unroll
    for (int n = 0; n < NCAM; n++) {
        if (!s_m[n]) continue;
#pragma unroll
        for (int l = 0; l < NLVL; l++) {
            int idx = n * 4 + l;
            const float* base = fp[l] + (size_t)(n * CDIM + t) * HWs[l];
            acc0 += s_w00[idx] * __ldg(base + s_o00[idx])
                  + s_w01[idx] * __ldg(base + s_o01[idx]);
            acc1 += s_w10[idx] * __ldg(base + s_o10[idx])
                  + s_w11[idx] * __ldg(base + s_o11[idx]);
        }
    }
    g_mid[q * CDIM + t] = acc0 + acc1;
}

// ---------------------------------------------------------------------------
// Tail helpers
// ---------------------------------------------------------------------------
// LayerNorm stats for QB queries at once: each of 256 threads holds p[r]
// (channel = threadIdx). Produces stat[r*2]=mean, stat[r*2+1]=rstd.
__device__ __forceinline__ void ln4(const float p[QB], float* redS, float* redQ,
                                    float* stat, int t) {
    int wid = t >> 5, lane = t & 31;
#pragma unroll
    for (int r = 0; r < QB; r++) {
        float s = p[r], ss = p[r] * p[r];
#pragma unroll
        for (int off = 16; off; off >>= 1) {
            s += __shfl_down_sync(0xffffffffu, s, off);
            ss += __shfl_down_sync(0xffffffffu, ss, off);
        }
        if (lane == 0) { redS[r * 8 + wid] = s; redQ[r * 8 + wid] = ss; }
    }
    __syncthreads();
    if (t < 32) {
        int r = t >> 3, w = t & 7;
        float s = redS[r * 8 + w], ss = redQ[r * 8 + w];
#pragma unroll
        for (int off = 4; off; off >>= 1) {
            s += __shfl_down_sync(0xffffffffu, s, off, 8);
            ss += __shfl_down_sync(0xffffffffu, ss, off, 8);
        }
        if (w == 0) {
            float m = s * (1.0f / 256.0f);
            float v = ss * (1.0f / 256.0f) - m * m;
            stat[r * 2] = m;
            stat[r * 2 + 1] = rsqrtf(v + EPSF);
        }
    }
    __syncthreads();
}

// o[r] = bias + sum_k sIn[r][k] * W[k*256 + t]    (256x256 weight, QB rows)
__device__ __forceinline__ void gemm4(const float* __restrict__ sIn,
                                      const float* __restrict__ W,
                                      float bias, float o[QB], int t) {
    o[0] = bias; o[1] = bias; o[2] = bias; o[3] = bias;
    const float4* A0 = (const float4*)(sIn);
    const float4* A1 = (const float4*)(sIn + 256);
    const float4* A2 = (const float4*)(sIn + 512);
    const float4* A3 = (const float4*)(sIn + 768);
#pragma unroll 4
    for (int kk = 0; kk < 64; kk++) {
        float w0 = __ldg(&W[(4 * kk + 0) * CDIM + t]);
        float w1 = __ldg(&W[(4 * kk + 1) * CDIM + t]);
        float w2 = __ldg(&W[(4 * kk + 2) * CDIM + t]);
        float w3 = __ldg(&W[(4 * kk + 3) * CDIM + t]);
        float4 a;
        a = A0[kk]; o[0] += a.x * w0 + a.y * w1 + a.z * w2 + a.w * w3;
        a = A1[kk]; o[1] += a.x * w0 + a.y * w1 + a.z * w2 + a.w * w3;
        a = A2[kk]; o[2] += a.x * w0 + a.y * w1 + a.z * w2 + a.w * w3;
        a = A3[kk]; o[3] += a.x * w0 + a.y * w1 + a.z * w2 + a.w * w3;
    }
}

// ---------------------------------------------------------------------------
// Kernel 3: pos-MLP (2x LN+relu) + mid@W_out + residuals + @W_fin + final LN
// QB=4 queries per block, 256 threads.
// ---------------------------------------------------------------------------
__global__ void __launch_bounds__(256) k_tail(
        const float* __restrict__ refp,
        const float* __restrict__ pe_w1, const float* __restrict__ pe_b1,
        const float* __restrict__ pe_g1, const float* __restrict__ pe_be1,
        const float* __restrict__ pe_w2, const float* __restrict__ pe_b2,
        const float* __restrict__ pe_g2, const float* __restrict__ pe_be2,
        const float* __restrict__ W_out, const float* __restrict__ b_out,
        const float* __restrict__ W_fin, const float* __restrict__ b_fin,
        const float* __restrict__ g_norm, const float* __restrict__ b_norm,
        float* __restrict__ outp) {
    int q0 = blockIdx.x * QB, t = threadIdx.x;
    __shared__ float sa[QB * CDIM];
    __shared__ float sb[QB * CDIM];
    __shared__ float redS[8 * QB], redQ[8 * QB];
    __shared__ float stat[QB * 2];

    // ---- pos layer 1: ref @ pe_w1 + b ----
    float p[QB];
    {
        float w0 = __ldg(&pe_w1[t]);
        float w1 = __ldg(&pe_w1[256 + t]);
        float w2 = __ldg(&pe_w1[512 + t]);
        float bb = __ldg(&pe_b1[t]);
#pragma unroll
        for (int r = 0; r < QB; r++) {
            float rx = __ldg(&refp[(q0 + r) * 3 + 0]);
            float ry = __ldg(&refp[(q0 + r) * 3 + 1]);
            float rz = __ldg(&refp[(q0 + r) * 3 + 2]);
            p[r] = bb + rx * w0 + ry * w1 + rz * w2;
        }
    }
    ln4(p, redS, redQ, stat, t);
    {
        float g = __ldg(&pe_g1[t]), be = __ldg(&pe_be1[t]);
#pragma unroll
        for (int r = 0; r < QB; r++)
            sa[r * 256 + t] = fmaxf((p[r] - stat[r * 2]) * stat[r * 2 + 1] * g + be, 0.0f);
    }
    __syncthreads();

    // ---- pos layer 2 ----
    float p2[QB];
    gemm4(sa, pe_w2, __ldg(&pe_b2[t]), p2, t);
    ln4(p2, redS, redQ, stat, t);   // internal syncs also fence sa reads
    float pos[QB];
    {
        float g = __ldg(&pe_g2[t]), be = __ldg(&pe_be2[t]);
#pragma unroll
        for (int r = 0; r < QB; r++)
            pos[r] = fmaxf((p2[r] - stat[r * 2]) * stat[r * 2 + 1] * g + be, 0.0f);
    }

    // ---- mid @ W_out ----
#pragma unroll
    for (int r = 0; r < QB; r++) sa[r * 256 + t] = g_mid[(q0 + r) * CDIM + t];
    __syncthreads();
    float o2[QB];
    gemm4(sa, W_out, __ldg(&b_out[t]), o2, t);

    // ---- sum = out + residual + pos ----
#pragma unroll
    for (int r = 0; r < QB; r++)
        sb[r * 256 + t] = o2[r] + g_qe[(q0 + r) * CDIM + t] + pos[r];
    __syncthreads();

    // ---- y = sum @ W_fin + b_fin  (QB x 64 outputs over 256 threads) ----
    int r = t >> 6, o = t & 63;
    float y = __ldg(&b_fin[o]);
    {
        const float4* S = (const float4*)(sb + r * 256);
#pragma unroll 4
        for (int kk = 0; kk < 64; kk++) {
            float4 s4 = S[kk];
            y += s4.x * __ldg(&W_fin[(4 * kk + 0) * 64 + o])
               + s4.y * __ldg(&W_fin[(4 * kk + 1) * 64 + o])
               + s4.z * __ldg(&W_fin[(4 * kk + 2) * 64 + o])
               + s4.w * __ldg(&W_fin[(4 * kk + 3) * 64 + o]);
        }
    }

    // ---- final LN over 64 (warps 2r, 2r+1 hold query r) ----
    {
        int wid = t >> 5, lane = t & 31;
        float s = y, ss = y * y;
#pragma unroll
        for (int off = 16; off; off >>= 1) {
            s += __shfl_down_sync(0xffffffffu, s, off);
            ss += __shfl_down_sync(0xffffffffu, ss, off);
        }
        if (lane == 0) { redS[wid] = s; redQ[wid] = ss; }
        __syncthreads();
        if (t < QB) {
            float sm = redS[2 * t] + redS[2 * t + 1];
            float sq = redQ[2 * t] + redQ[2 * t + 1];
            float m = sm * (1.0f / 64.0f);
            float v = sq * (1.0f / 64.0f) - m * m;
            stat[t * 2] = m;
            stat[t * 2 + 1] = rsqrtf(v + EPSF);
        }
        __syncthreads();
        outp[(q0 + r) * 64 + o] =
            (y - stat[r * 2]) * stat[r * 2 + 1] * __ldg(&g_norm[o]) + __ldg(&b_norm[o]);
    }
}

// ---------------------------------------------------------------------------
extern "C" void kernel_launch(void* const* d_in, const int* in_sizes, int n_in,
                              void* d_out, int out_size) {
    const float* query   = (const float*)d_in[0];
    const float* qpos    = (const float*)d_in[1];
    const float* refp    = (const float*)d_in[2];
    const float* l2i     = (const float*)d_in[3];
    const float* f0      = (const float*)d_in[4];
    const float* f1      = (const float*)d_in[5];
    const float* f2      = (const float*)d_in[6];
    const float* f3      = (const float*)d_in[7];
    const float* W_qe    = (const float*)d_in[8];
    const float* b_qe    = (const float*)d_in[9];
    const float* W_attn  = (const float*)d_in[10];
    const float* b_attn  = (const float*)d_in[11];
    const float* W_out   = (const float*)d_in[12];
    const float* b_out   = (const float*)d_in[13];
    const float* pe_w1   = (const float*)d_in[14];
    const float* pe_b1   = (const float*)d_in[15];
    const float* pe_g1   = (const float*)d_in[16];
    const float* pe_be1  = (const float*)d_in[17];
    const float* pe_w2   = (const float*)d_in[18];
    const float* pe_b2   = (const float*)d_in[19];
    const float* pe_g2   = (const float*)d_in[20];
    const float* pe_be2  = (const float*)d_in[21];
    const float* W_fin   = (const float*)d_in[22];
    const float* b_fin   = (const float*)d_in[23];
    const float* g_norm  = (const float*)d_in[24];
    const float* b_norm  = (const float*)d_in[25];
    float* outp = (float*)d_out;

    k_qe<<<NQ / QB, 256>>>(query, qpos, W_qe, b_qe, W_attn, b_attn);
    k_gather<<<NQ, 256>>>(refp, l2i, f0, f1, f2, f3);
    k_tail<<<NQ / QB, 256>>>(refp, pe_w1, pe_b1, pe_g1, pe_be1,
                             pe_w2, pe_b2, pe_g2, pe_be2,
                             W_out, b_out, W_fin, b_fin, g_norm, b_norm, outp);
}